// round 1
// baseline (speedup 1.0000x reference)
#include <cuda_runtime.h>
#include <math.h>

// Problem constants (fixed by setup_inputs)
#define BB      4
#define CDIM    64
#define HH      128
#define WWID    128
#define HW      (HH * WWID)
#define DD      256
#define NBOX    100
#define MAXDET  10
#define TOPK    5
#define CONF_T  0.2f
#define IOU_T   0.4f

// Output packing (flattened concat, float32):
//   seg_output : (H*W, B, 1) -> 65536
//   mask_maps  : (B, H, W)   -> 65536
//   kept       : (B, 10, 5)  -> 200
//   valid      : (B, 10)     -> 40
#define SEG_OFF   0
#define MASK_OFF  (HW * BB)
#define KEPT_OFF  (MASK_OFF + BB * HW)
#define VALID_OFF (KEPT_OFF + BB * MAXDET * 5)
#define OUT_TOTAL (VALID_OFF + BB * MAXDET)

#define TILE    16
#define MAXPIX  16384   // theoretical max inside pixels = 17*17*10*4 = 11560

// Device scratch (no dynamic allocation allowed)
__device__ int   g_count;
__device__ int   g_list[MAXPIX];
__device__ float g_seg0;
__device__ int   g_box[BB * MAXDET * 5];  // x1,y1,x2,y2,valid per kept box

// ---------------------------------------------------------------------------
// Kernel 1: NMS per batch. 1 block per batch, 128 threads.
// Exactly mirrors the JAX greedy scan semantics (first-index argmax ties,
// suppression mask, has-guard, validity post-filters).
// ---------------------------------------------------------------------------
__global__ void nms_kernel(const float* __restrict__ boxes, float* __restrict__ out,
                           int out_size) {
    const int b = blockIdx.x;
    const int t = threadIdx.x;

    __shared__ float bx[NBOX][5];
    __shared__ float area[NBOX];
    __shared__ unsigned char cand[NBOX];
    __shared__ float s_score[128];
    __shared__ int   s_idx[128];
    __shared__ int   keptidx[MAXDET];
    __shared__ unsigned char hasarr[MAXDET];
    __shared__ int any_pass;

    if (b == 0 && t == 0) g_count = 0;   // reset compaction counter each call

    for (int i = t; i < NBOX * 5; i += 128)
        bx[i / 5][i % 5] = boxes[b * NBOX * 5 + i];
    if (t == 0) any_pass = 0;
    __syncthreads();

    if (t < NBOX) {
        area[t] = fmaxf(bx[t][2] - bx[t][0], 0.f) * fmaxf(bx[t][3] - bx[t][1], 0.f);
        if (bx[t][4] > CONF_T) any_pass = 1;
    }
    __syncthreads();
    if (t < NBOX)
        cand[t] = any_pass ? (bx[t][4] > CONF_T ? 1 : 0) : 1;
    __syncthreads();

    for (int it = 0; it < MAXDET; it++) {
        float sc = (t < NBOX && cand[t]) ? bx[t][4] : -INFINITY;
        s_score[t] = sc;
        s_idx[t] = t;
        __syncthreads();
        // argmax with first-index tiebreak
        for (int off = 64; off > 0; off >>= 1) {
            if (t < off) {
                float s2 = s_score[t + off];
                int i2 = s_idx[t + off];
                if (s2 > s_score[t] || (s2 == s_score[t] && i2 < s_idx[t])) {
                    s_score[t] = s2;
                    s_idx[t] = i2;
                }
            }
            __syncthreads();
        }
        int idx = s_idx[0];
        bool has = (s_score[0] > -INFINITY);
        if (t == 0) { keptidx[it] = idx; hasarr[it] = has ? 1 : 0; }

        if (has && t < NBOX) {
            float lt0 = fmaxf(bx[idx][0], bx[t][0]);
            float lt1 = fmaxf(bx[idx][1], bx[t][1]);
            float rb0 = fminf(bx[idx][2], bx[t][2]);
            float rb1 = fminf(bx[idx][3], bx[t][3]);
            float iw = fmaxf(rb0 - lt0, 0.f);
            float ih = fmaxf(rb1 - lt1, 0.f);
            float inter = iw * ih;
            float iou = inter / (area[idx] + area[t] - inter + 1e-9f);
            unsigned char nc = (cand[t] && !(iou > IOU_T)) ? 1 : 0;
            if (t == idx) nc = 0;
            cand[t] = nc;
        }
        __syncthreads();
    }

    // Write kept boxes (all 5 columns)
    if (t < MAXDET * 5) {
        int d = t / 5, c = t % 5;
        int o = KEPT_OFF + (b * MAXDET + d) * 5 + c;
        if (o < out_size) out[o] = bx[keptidx[d]][c];
    }
    // Validity + integer clipped coords
    if (t < MAXDET) {
        int idx = keptidx[t];
        float kx1 = bx[idx][0], ky1 = bx[idx][1];
        float kx2 = bx[idx][2], ky2 = bx[idx][3];
        bool v = hasarr[t] != 0;
        v = v && (kx2 - kx1 >= 1.f) && (ky2 - ky1 >= 1.f);
        v = v && (any_pass ? true : (t < TOPK));

        int ix1 = min(max((int)floorf(kx1 + 0.5f), 0), WWID);
        int iy1 = min(max((int)floorf(ky1 + 0.5f), 0), HH);
        int ix2 = min(max((int)floorf(kx2 + 0.5f), 0), WWID);
        int iy2 = min(max((int)floorf(ky2 + 0.5f), 0), HH);

        int base = (b * MAXDET + t) * 5;
        g_box[base + 0] = ix1;
        g_box[base + 1] = iy1;
        g_box[base + 2] = ix2;
        g_box[base + 3] = iy2;
        g_box[base + 4] = v ? 1 : 0;

        int o = VALID_OFF + b * MAXDET + t;
        if (o < out_size) out[o] = v ? 1.f : 0.f;
    }
}

// ---------------------------------------------------------------------------
// Kernel 2: zero-input MLP -> scalar g_seg0. One block, 256 threads.
// h1 = relu(b1); h2 = relu(h1 @ W2 + b2); seg0 = h2 @ W3 + b3[0]
// ---------------------------------------------------------------------------
__global__ void seg0_kernel(const float* __restrict__ W2, const float* __restrict__ b1,
                            const float* __restrict__ b2, const float* __restrict__ W3,
                            const float* __restrict__ b3) {
    __shared__ float h1s[DD];
    __shared__ float red[8];
    int t = threadIdx.x;
    h1s[t] = fmaxf(b1[t], 0.f);
    __syncthreads();
    float acc = b2[t];
    #pragma unroll 4
    for (int k = 0; k < DD; k++) acc += h1s[k] * W2[k * DD + t];
    float v = fmaxf(acc, 0.f) * W3[t];
    #pragma unroll
    for (int off = 16; off > 0; off >>= 1)
        v += __shfl_down_sync(0xffffffffu, v, off);
    if ((t & 31) == 0) red[t >> 5] = v;
    __syncthreads();
    if (t == 0) {
        float s = 0.f;
        #pragma unroll
        for (int w = 0; w < 8; w++) s += red[w];
        g_seg0 = s + b3[0];
    }
}

// ---------------------------------------------------------------------------
// Kernel 3: per-pixel mask + default seg fill + inside-pixel compaction.
// ---------------------------------------------------------------------------
__global__ void mask_kernel(float* __restrict__ out, int out_size) {
    int id = blockIdx.x * blockDim.x + threadIdx.x;
    if (id >= BB * HW) return;
    int b = id / HW, pix = id % HW;
    int h = pix / WWID, w = pix % WWID;

    bool inside = false;
    #pragma unroll
    for (int d = 0; d < MAXDET; d++) {
        int base = (b * MAXDET + d) * 5;
        int vx1 = g_box[base + 0], vy1 = g_box[base + 1];
        int vx2 = g_box[base + 2], vy2 = g_box[base + 3];
        int vv  = g_box[base + 4];
        if (vv && w >= vx1 && w < vx2 && h >= vy1 && h < vy2) inside = true;
    }

    int mo = MASK_OFF + id;
    if (mo < out_size) out[mo] = inside ? 0.f : 1.f;
    int so = SEG_OFF + pix * BB + b;
    if (so < out_size) out[so] = g_seg0;   // default; overwritten if inside

    if (inside) {
        int pos = atomicAdd(&g_count, 1);
        if (pos < MAXPIX) g_list[pos] = id;
    }
}

// ---------------------------------------------------------------------------
// Kernel 4: fused seman + 3-layer MLP on compacted inside pixels.
// TILE=16 pixels per block, 256 threads (thread = output neuron j).
// ---------------------------------------------------------------------------
__global__ __launch_bounds__(256)
void mlp_kernel(const float* __restrict__ x,
                const float* __restrict__ W_sem, const float* __restrict__ b_sem,
                const float* __restrict__ W1, const float* __restrict__ b1,
                const float* __restrict__ W2, const float* __restrict__ b2,
                const float* __restrict__ W3, const float* __restrict__ b3,
                float* __restrict__ out, int out_size) {
    int cnt = g_count;
    if (cnt > MAXPIX) cnt = MAXPIX;
    int start = blockIdx.x * TILE;
    if (start >= cnt) return;
    int m = min(TILE, cnt - start);

    __shared__ float xs[TILE][CDIM];   // gathered x channels
    __shared__ float ws[TILE][DD];     // words -> h1 (reused)
    __shared__ int   plist[TILE];
    __shared__ float wred[8][TILE];

    const int t = threadIdx.x;
    if (t < TILE) plist[t] = (t < m) ? g_list[start + t] : -1;
    __syncthreads();

    // gather x[b, :, pix] for each tile pixel
    for (int i = t; i < TILE * CDIM; i += 256) {
        int p = i / CDIM, c = i % CDIM;
        int id = plist[p];
        float v = 0.f;
        if (id >= 0) {
            int b = id / HW, pix = id % HW;
            v = x[(b * CDIM + c) * HW + pix];
        }
        xs[p][c] = v;
    }
    __syncthreads();

    float acc[TILE];

    // ---- seman: words[p][t] = b_sem[t] + sum_c xs[p][c] * W_sem[c][t]
    {
        float bj = b_sem[t];
        #pragma unroll
        for (int p = 0; p < TILE; p++) acc[p] = bj;
        for (int c = 0; c < CDIM; c += 4) {
            float w0 = W_sem[(c + 0) * DD + t];
            float w1 = W_sem[(c + 1) * DD + t];
            float w2 = W_sem[(c + 2) * DD + t];
            float w3 = W_sem[(c + 3) * DD + t];
            #pragma unroll
            for (int p = 0; p < TILE; p++) {
                float4 xv = *(const float4*)&xs[p][c];
                acc[p] += xv.x * w0 + xv.y * w1 + xv.z * w2 + xv.w * w3;
            }
        }
        #pragma unroll
        for (int p = 0; p < TILE; p++) ws[p][t] = acc[p];  // no relu on seman
    }
    __syncthreads();

    // ---- layer 1: h1 = relu(words @ W1 + b1)
    {
        float bj = b1[t];
        #pragma unroll
        for (int p = 0; p < TILE; p++) acc[p] = bj;
        for (int k = 0; k < DD; k += 4) {
            float w0 = W1[(k + 0) * DD + t];
            float w1 = W1[(k + 1) * DD + t];
            float w2 = W1[(k + 2) * DD + t];
            float w3 = W1[(k + 3) * DD + t];
            #pragma unroll
            for (int p = 0; p < TILE; p++) {
                float4 wv = *(const float4*)&ws[p][k];
                acc[p] += wv.x * w0 + wv.y * w1 + wv.z * w2 + wv.w * w3;
            }
        }
        __syncthreads();  // all reads of ws done before overwrite
        #pragma unroll
        for (int p = 0; p < TILE; p++) ws[p][t] = fmaxf(acc[p], 0.f);
    }
    __syncthreads();

    // ---- layer 2: h2 = relu(h1 @ W2 + b2)  (kept in registers)
    {
        float bj = b2[t];
        #pragma unroll
        for (int p = 0; p < TILE; p++) acc[p] = bj;
        for (int k = 0; k < DD; k += 4) {
            float w0 = W2[(k + 0) * DD + t];
            float w1 = W2[(k + 1) * DD + t];
            float w2 = W2[(k + 2) * DD + t];
            float w3 = W2[(k + 3) * DD + t];
            #pragma unroll
            for (int p = 0; p < TILE; p++) {
                float4 wv = *(const float4*)&ws[p][k];
                acc[p] += wv.x * w0 + wv.y * w1 + wv.z * w2 + wv.w * w3;
            }
        }
    }

    // ---- layer 3: seg[p] = sum_j relu(h2[p][j]) * W3[j] + b3[0]
    {
        float w3j = W3[t];
        int lane = t & 31, warp = t >> 5;
        #pragma unroll
        for (int p = 0; p < TILE; p++) {
            float v = fmaxf(acc[p], 0.f) * w3j;
            #pragma unroll
            for (int off = 16; off > 0; off >>= 1)
                v += __shfl_down_sync(0xffffffffu, v, off);
            if (lane == 0) wred[warp][p] = v;
        }
        __syncthreads();
        if (t < TILE) {
            float s = b3[0];
            #pragma unroll
            for (int w = 0; w < 8; w++) s += wred[w][t];
            int id = plist[t];
            if (id >= 0) {
                int b = id / HW, pix = id % HW;
                int so = SEG_OFF + pix * BB + b;
                if (so < out_size) out[so] = s;
            }
        }
    }
}

// ---------------------------------------------------------------------------
extern "C" void kernel_launch(void* const* d_in, const int* in_sizes, int n_in,
                              void* d_out, int out_size) {
    const float* x      = (const float*)d_in[0];
    const float* rboxes = (const float*)d_in[1];
    const float* W_sem  = (const float*)d_in[2];
    const float* b_sem  = (const float*)d_in[3];
    const float* W1     = (const float*)d_in[4];
    const float* b1     = (const float*)d_in[5];
    const float* W2     = (const float*)d_in[6];
    const float* b2     = (const float*)d_in[7];
    const float* W3     = (const float*)d_in[8];
    const float* b3     = (const float*)d_in[9];
    float* out = (float*)d_out;

    nms_kernel<<<BB, 128>>>(rboxes, out, out_size);
    seg0_kernel<<<1, DD>>>(W2, b1, b2, W3, b3);
    mask_kernel<<<(BB * HW + 255) / 256, 256>>>(out, out_size);
    mlp_kernel<<<MAXPIX / TILE, 256>>>(x, W_sem, b_sem, W1, b1, W2, b2, W3, b3,
                                       out, out_size);
}

// round 2
// speedup vs baseline: 1.1380x; 1.1380x over previous
#include <cuda_runtime.h>
#include <math.h>

// Problem constants (fixed by setup_inputs)
#define BB      4
#define CDIM    64
#define HH      128
#define WWID    128
#define HW      (HH * WWID)
#define DD      256
#define NBOX    100
#define MAXDET  10
#define TOPK    5
#define CONF_T  0.2f
#define IOU_T   0.4f

// Output packing (flattened concat, float32):
//   seg_output : (H*W, B, 1) -> 65536
//   mask_maps  : (B, H, W)   -> 65536
//   kept       : (B, 10, 5)  -> 200
//   valid      : (B, 10)     -> 40
#define SEG_OFF   0
#define MASK_OFF  (HW * BB)
#define KEPT_OFF  (MASK_OFF + BB * HW)
#define VALID_OFF (KEPT_OFF + BB * MAXDET * 5)

#define TILE    12
#define MAXPIX  16384   // theoretical max inside pixels = 17*17*10*4 = 11560

// Device scratch (no dynamic allocation allowed)
__device__ int   g_count;
__device__ int   g_list[MAXPIX];
__device__ float g_seg0;
__device__ int   g_box[BB * MAXDET * 5];  // x1,y1,x2,y2,valid per kept box

// ---------------------------------------------------------------------------
// Kernel 1: NMS per batch. 1 block per batch, 128 threads.
// ---------------------------------------------------------------------------
__global__ void nms_kernel(const float* __restrict__ boxes, float* __restrict__ out,
                           int out_size) {
    const int b = blockIdx.x;
    const int t = threadIdx.x;

    __shared__ float bx[NBOX][5];
    __shared__ float area[NBOX];
    __shared__ unsigned char cand[NBOX];
    __shared__ float s_score[128];
    __shared__ int   s_idx[128];
    __shared__ int   keptidx[MAXDET];
    __shared__ unsigned char hasarr[MAXDET];
    __shared__ int any_pass;

    if (b == 0 && t == 0) g_count = 0;   // reset compaction counter each call

    for (int i = t; i < NBOX * 5; i += 128)
        bx[i / 5][i % 5] = boxes[b * NBOX * 5 + i];
    if (t == 0) any_pass = 0;
    __syncthreads();

    if (t < NBOX) {
        area[t] = fmaxf(bx[t][2] - bx[t][0], 0.f) * fmaxf(bx[t][3] - bx[t][1], 0.f);
        if (bx[t][4] > CONF_T) any_pass = 1;
    }
    __syncthreads();
    if (t < NBOX)
        cand[t] = any_pass ? (bx[t][4] > CONF_T ? 1 : 0) : 1;
    __syncthreads();

    for (int it = 0; it < MAXDET; it++) {
        float sc = (t < NBOX && cand[t]) ? bx[t][4] : -INFINITY;
        s_score[t] = sc;
        s_idx[t] = t;
        __syncthreads();
        for (int off = 64; off > 0; off >>= 1) {
            if (t < off) {
                float s2 = s_score[t + off];
                int i2 = s_idx[t + off];
                if (s2 > s_score[t] || (s2 == s_score[t] && i2 < s_idx[t])) {
                    s_score[t] = s2;
                    s_idx[t] = i2;
                }
            }
            __syncthreads();
        }
        int idx = s_idx[0];
        bool has = (s_score[0] > -INFINITY);
        if (t == 0) { keptidx[it] = idx; hasarr[it] = has ? 1 : 0; }

        if (has && t < NBOX) {
            float lt0 = fmaxf(bx[idx][0], bx[t][0]);
            float lt1 = fmaxf(bx[idx][1], bx[t][1]);
            float rb0 = fminf(bx[idx][2], bx[t][2]);
            float rb1 = fminf(bx[idx][3], bx[t][3]);
            float iw = fmaxf(rb0 - lt0, 0.f);
            float ih = fmaxf(rb1 - lt1, 0.f);
            float inter = iw * ih;
            float iou = inter / (area[idx] + area[t] - inter + 1e-9f);
            unsigned char nc = (cand[t] && !(iou > IOU_T)) ? 1 : 0;
            if (t == idx) nc = 0;
            cand[t] = nc;
        }
        __syncthreads();
    }

    if (t < MAXDET * 5) {
        int d = t / 5, c = t % 5;
        int o = KEPT_OFF + (b * MAXDET + d) * 5 + c;
        if (o < out_size) out[o] = bx[keptidx[d]][c];
    }
    if (t < MAXDET) {
        int idx = keptidx[t];
        float kx1 = bx[idx][0], ky1 = bx[idx][1];
        float kx2 = bx[idx][2], ky2 = bx[idx][3];
        bool v = hasarr[t] != 0;
        v = v && (kx2 - kx1 >= 1.f) && (ky2 - ky1 >= 1.f);
        v = v && (any_pass ? true : (t < TOPK));

        int ix1 = min(max((int)floorf(kx1 + 0.5f), 0), WWID);
        int iy1 = min(max((int)floorf(ky1 + 0.5f), 0), HH);
        int ix2 = min(max((int)floorf(kx2 + 0.5f), 0), WWID);
        int iy2 = min(max((int)floorf(ky2 + 0.5f), 0), HH);

        int base = (b * MAXDET + t) * 5;
        g_box[base + 0] = ix1;
        g_box[base + 1] = iy1;
        g_box[base + 2] = ix2;
        g_box[base + 3] = iy2;
        g_box[base + 4] = v ? 1 : 0;

        int o = VALID_OFF + b * MAXDET + t;
        if (o < out_size) out[o] = v ? 1.f : 0.f;
    }
}

// ---------------------------------------------------------------------------
// Kernel 2: zero-input MLP -> scalar g_seg0.
// ---------------------------------------------------------------------------
__global__ void seg0_kernel(const float* __restrict__ W2, const float* __restrict__ b1,
                            const float* __restrict__ b2, const float* __restrict__ W3,
                            const float* __restrict__ b3) {
    __shared__ float h1s[DD];
    __shared__ float red[8];
    int t = threadIdx.x;
    h1s[t] = fmaxf(b1[t], 0.f);
    __syncthreads();
    float acc = b2[t];
    #pragma unroll 4
    for (int k = 0; k < DD; k++) acc += h1s[k] * W2[k * DD + t];
    float v = fmaxf(acc, 0.f) * W3[t];
    #pragma unroll
    for (int off = 16; off > 0; off >>= 1)
        v += __shfl_down_sync(0xffffffffu, v, off);
    if ((t & 31) == 0) red[t >> 5] = v;
    __syncthreads();
    if (t == 0) {
        float s = 0.f;
        #pragma unroll
        for (int w = 0; w < 8; w++) s += red[w];
        g_seg0 = s + b3[0];
    }
}

// ---------------------------------------------------------------------------
// Kernel 3: per-pixel mask + default seg fill + inside-pixel compaction.
// ---------------------------------------------------------------------------
__global__ void mask_kernel(float* __restrict__ out, int out_size) {
    int id = blockIdx.x * blockDim.x + threadIdx.x;
    if (id >= BB * HW) return;
    int b = id / HW, pix = id % HW;
    int h = pix / WWID, w = pix % WWID;

    bool inside = false;
    #pragma unroll
    for (int d = 0; d < MAXDET; d++) {
        int base = (b * MAXDET + d) * 5;
        int vx1 = g_box[base + 0], vy1 = g_box[base + 1];
        int vx2 = g_box[base + 2], vy2 = g_box[base + 3];
        int vv  = g_box[base + 4];
        if (vv && w >= vx1 && w < vx2 && h >= vy1 && h < vy2) inside = true;
    }

    int mo = MASK_OFF + id;
    if (mo < out_size) out[mo] = inside ? 0.f : 1.f;
    int so = SEG_OFF + pix * BB + b;
    if (so < out_size) out[so] = g_seg0;   // default; overwritten if inside

    if (inside) {
        int pos = atomicAdd(&g_count, 1);
        if (pos < MAXPIX) g_list[pos] = id;
    }
}

// ---------------------------------------------------------------------------
// Kernel 4: fused seman + 3-layer MLP on compacted inside pixels.
// TILE=12 pixels/block, 256 threads (thread = output neuron j).
// Software-pipelined weight loads (8 outstanding LDGs, double-buffered regs).
// ---------------------------------------------------------------------------
__global__ __launch_bounds__(256)
void mlp_kernel(const float* __restrict__ x,
                const float* __restrict__ W_sem, const float* __restrict__ b_sem,
                const float* __restrict__ W1, const float* __restrict__ b1,
                const float* __restrict__ W2, const float* __restrict__ b2,
                const float* __restrict__ W3, const float* __restrict__ b3,
                float* __restrict__ out, int out_size) {
    int cnt = g_count;
    if (cnt > MAXPIX) cnt = MAXPIX;
    int start = blockIdx.x * TILE;
    if (start >= cnt) return;
    int m = min(TILE, cnt - start);

    __shared__ float xs[TILE][CDIM];   // gathered x channels
    __shared__ float ws[TILE][DD];     // words -> h1 (reused)
    __shared__ int   plist[TILE];
    __shared__ float wred[8][TILE];

    const int t = threadIdx.x;
    if (t < TILE) plist[t] = (t < m) ? g_list[start + t] : -1;
    __syncthreads();

    // gather x[b, :, pix] for each tile pixel
    for (int i = t; i < TILE * CDIM; i += 256) {
        int p = i / CDIM, c = i % CDIM;
        int id = plist[p];
        float v = 0.f;
        if (id >= 0) {
            int b = id / HW, pix = id % HW;
            v = x[(b * CDIM + c) * HW + pix];
        }
        xs[p][c] = v;
    }
    __syncthreads();

    float acc[TILE];
    float w[8], wn[8];

    // ---- seman: words[p][t] = b_sem[t] + sum_c xs[p][c] * W_sem[c][t]
    {
        const float* Wp = W_sem + t;
        float bj = b_sem[t];
        #pragma unroll
        for (int p = 0; p < TILE; p++) acc[p] = bj;

        #pragma unroll
        for (int i = 0; i < 8; i++) w[i] = Wp[i * DD];

        #pragma unroll 1
        for (int k0 = 0; k0 < CDIM - 8; k0 += 8) {
            #pragma unroll
            for (int i = 0; i < 8; i++) wn[i] = Wp[(k0 + 8 + i) * DD];
            #pragma unroll
            for (int i = 0; i < 8; i += 4) {
                #pragma unroll
                for (int p = 0; p < TILE; p++) {
                    float4 xv = *(const float4*)&xs[p][k0 + i];
                    acc[p] += xv.x * w[i] + xv.y * w[i + 1]
                            + xv.z * w[i + 2] + xv.w * w[i + 3];
                }
            }
            #pragma unroll
            for (int i = 0; i < 8; i++) w[i] = wn[i];
        }
        // final chunk
        {
            const int k0 = CDIM - 8;
            #pragma unroll
            for (int i = 0; i < 8; i += 4) {
                #pragma unroll
                for (int p = 0; p < TILE; p++) {
                    float4 xv = *(const float4*)&xs[p][k0 + i];
                    acc[p] += xv.x * w[i] + xv.y * w[i + 1]
                            + xv.z * w[i + 2] + xv.w * w[i + 3];
                }
            }
        }
        #pragma unroll
        for (int p = 0; p < TILE; p++) ws[p][t] = acc[p];  // no relu on seman
    }
    __syncthreads();

    // ---- layer 1: h1 = relu(words @ W1 + b1)
    {
        const float* Wp = W1 + t;
        float bj = b1[t];
        #pragma unroll
        for (int p = 0; p < TILE; p++) acc[p] = bj;

        #pragma unroll
        for (int i = 0; i < 8; i++) w[i] = Wp[i * DD];

        #pragma unroll 1
        for (int k0 = 0; k0 < DD - 8; k0 += 8) {
            #pragma unroll
            for (int i = 0; i < 8; i++) wn[i] = Wp[(k0 + 8 + i) * DD];
            #pragma unroll
            for (int i = 0; i < 8; i += 4) {
                #pragma unroll
                for (int p = 0; p < TILE; p++) {
                    float4 wv = *(const float4*)&ws[p][k0 + i];
                    acc[p] += wv.x * w[i] + wv.y * w[i + 1]
                            + wv.z * w[i + 2] + wv.w * w[i + 3];
                }
            }
            #pragma unroll
            for (int i = 0; i < 8; i++) w[i] = wn[i];
        }
        {
            const int k0 = DD - 8;
            #pragma unroll
            for (int i = 0; i < 8; i += 4) {
                #pragma unroll
                for (int p = 0; p < TILE; p++) {
                    float4 wv = *(const float4*)&ws[p][k0 + i];
                    acc[p] += wv.x * w[i] + wv.y * w[i + 1]
                            + wv.z * w[i + 2] + wv.w * w[i + 3];
                }
            }
        }
        __syncthreads();  // all reads of ws done before overwrite
        #pragma unroll
        for (int p = 0; p < TILE; p++) ws[p][t] = fmaxf(acc[p], 0.f);
    }
    __syncthreads();

    // ---- layer 2: h2 = relu(h1 @ W2 + b2)  (kept in registers)
    {
        const float* Wp = W2 + t;
        float bj = b2[t];
        #pragma unroll
        for (int p = 0; p < TILE; p++) acc[p] = bj;

        #pragma unroll
        for (int i = 0; i < 8; i++) w[i] = Wp[i * DD];

        #pragma unroll 1
        for (int k0 = 0; k0 < DD - 8; k0 += 8) {
            #pragma unroll
            for (int i = 0; i < 8; i++) wn[i] = Wp[(k0 + 8 + i) * DD];
            #pragma unroll
            for (int i = 0; i < 8; i += 4) {
                #pragma unroll
                for (int p = 0; p < TILE; p++) {
                    float4 wv = *(const float4*)&ws[p][k0 + i];
                    acc[p] += wv.x * w[i] + wv.y * w[i + 1]
                            + wv.z * w[i + 2] + wv.w * w[i + 3];
                }
            }
            #pragma unroll
            for (int i = 0; i < 8; i++) w[i] = wn[i];
        }
        {
            const int k0 = DD - 8;
            #pragma unroll
            for (int i = 0; i < 8; i += 4) {
                #pragma unroll
                for (int p = 0; p < TILE; p++) {
                    float4 wv = *(const float4*)&ws[p][k0 + i];
                    acc[p] += wv.x * w[i] + wv.y * w[i + 1]
                            + wv.z * w[i + 2] + wv.w * w[i + 3];
                }
            }
        }
    }

    // ---- layer 3: seg[p] = sum_j relu(h2[p][j]) * W3[j] + b3[0]
    {
        float w3j = W3[t];
        int lane = t & 31, warp = t >> 5;
        #pragma unroll
        for (int p = 0; p < TILE; p++) {
            float v = fmaxf(acc[p], 0.f) * w3j;
            #pragma unroll
            for (int off = 16; off > 0; off >>= 1)
                v += __shfl_down_sync(0xffffffffu, v, off);
            if (lane == 0) wred[warp][p] = v;
        }
        __syncthreads();
        if (t < TILE) {
            float s = b3[0];
            #pragma unroll
            for (int w8 = 0; w8 < 8; w8++) s += wred[w8][t];
            int id = plist[t];
            if (id >= 0) {
                int b = id / HW, pix = id % HW;
                int so = SEG_OFF + pix * BB + b;
                if (so < out_size) out[so] = s;
            }
        }
    }
}

// ---------------------------------------------------------------------------
extern "C" void kernel_launch(void* const* d_in, const int* in_sizes, int n_in,
                              void* d_out, int out_size) {
    const float* x      = (const float*)d_in[0];
    const float* rboxes = (const float*)d_in[1];
    const float* W_sem  = (const float*)d_in[2];
    const float* b_sem  = (const float*)d_in[3];
    const float* W1     = (const float*)d_in[4];
    const float* b1     = (const float*)d_in[5];
    const float* W2     = (const float*)d_in[6];
    const float* b2     = (const float*)d_in[7];
    const float* W3     = (const float*)d_in[8];
    const float* b3     = (const float*)d_in[9];
    float* out = (float*)d_out;

    nms_kernel<<<BB, 128>>>(rboxes, out, out_size);
    seg0_kernel<<<1, DD>>>(W2, b1, b2, W3, b3);
    mask_kernel<<<(BB * HW + 255) / 256, 256>>>(out, out_size);
    mlp_kernel<<<(MAXPIX + TILE - 1) / TILE, 256>>>(x, W_sem, b_sem,
                                                    W1, b1, W2, b2, W3, b3,
                                                    out, out_size);
}